// round 16
// baseline (speedup 1.0000x reference)
#include <cuda_runtime.h>
#include <cuda_fp16.h>
#include <cstdint>

#define N_NODES 100000
#define N_EDGES 625000
#define EMB     128
#define SCALE   0.4f   // alpha/2
#define CAP     24     // Poisson(6.25): P(deg>=24) ~ 4e-9 per node; guarded anyway

#define SCAT_BLOCKS  ((N_EDGES + 255) / 256)             // 2442
#define CONV_THREADS (N_NODES * EMB / 8)                  // 1,600,000 (8 elems/thread)
#define CONV_BLOCKS  ((CONV_THREADS + 255) / 256)         // 6250

// Device scratch (allocation-free rule: __device__ globals)
__device__ int    g_count[N_NODES];               // degree histogram == alloc cursor
__device__ float2 g_edge[(size_t)N_NODES * CAP];  // (col bits, pre-scaled val)
__device__ __half g_xh[(size_t)N_NODES * EMB];    // fp16 copy of x, 25.6 MB

// ---- 1. fused build: scatter blocks + x->fp16 convert blocks in ONE launch ----
__global__ void build_kernel(const float* __restrict__ vals,
                             const int*  __restrict__ rows,
                             const int*  __restrict__ cols,
                             const float* __restrict__ x) {
    int b = blockIdx.x;
    if (b < SCAT_BLOCKS) {
        int i = b * 256 + threadIdx.x;
        if (i < N_EDGES) {
            int   r = rows[i];
            int   c = cols[i];
            float v = vals[i] * SCALE;
            int p = atomicAdd(&g_count[r], 1);
            if (p < CAP) g_edge[(size_t)r * CAP + p] = make_float2(__int_as_float(c), v);
        }
    } else {
        int i = (b - SCAT_BLOCKS) * 256 + threadIdx.x;   // 8 floats per thread
        if (i < CONV_THREADS) {
            float4 a0 = reinterpret_cast<const float4*>(x)[i * 2];
            float4 a1 = reinterpret_cast<const float4*>(x)[i * 2 + 1];
            __half2 h0 = __floats2half2_rn(a0.x, a0.y);
            __half2 h1 = __floats2half2_rn(a0.z, a0.w);
            __half2 h2 = __floats2half2_rn(a1.x, a1.y);
            __half2 h3 = __floats2half2_rn(a1.z, a1.w);
            uint4 o;
            o.x = *reinterpret_cast<uint32_t*>(&h0);
            o.y = *reinterpret_cast<uint32_t*>(&h1);
            o.z = *reinterpret_cast<uint32_t*>(&h2);
            o.w = *reinterpret_cast<uint32_t*>(&h3);
            reinterpret_cast<uint4*>(g_xh)[i] = o;
        }
    }
}

// ---- 2. gather: one warp/node, two stall waves, 8 gathers in flight ----
// Wave 1: deg + 4 meta float4s + x[n] + e[n] (7 independent loads).
// Wave 2: 8 fp16 neighbor-row gathers (8B/lane). Slots >= deg are zero-init
// (col=0, safe) and masked by v=0. Tail loop only for deg > 8 (~18% of nodes).
__global__ void __launch_bounds__(256, 6) gather_kernel(
        const float* __restrict__ x,
        const float* __restrict__ emb,
        float* __restrict__ out) {
    int lane = threadIdx.x & 31;
    int n = (blockIdx.x * blockDim.x + threadIdx.x) >> 5;
    if (n >= N_NODES) return;

    const float2* ebase = g_edge + (size_t)n * CAP;

    // ---- wave 1: issue everything independent ----
    int    deg = g_count[n];
    float4 m01 = *reinterpret_cast<const float4*>(ebase);       // slots 0,1
    float4 m23 = *reinterpret_cast<const float4*>(ebase + 2);   // slots 2,3
    float4 m45 = *reinterpret_cast<const float4*>(ebase + 4);   // slots 4,5
    float4 m67 = *reinterpret_cast<const float4*>(ebase + 6);   // slots 6,7
    float4 xv  = reinterpret_cast<const float4*>(x   + (size_t)n * EMB)[lane];
    float4 ev  = reinterpret_cast<const float4*>(emb + (size_t)n * EMB)[lane];

    if (deg > CAP) deg = CAP;

    int c0 = __float_as_int(m01.x), c1 = __float_as_int(m01.z);
    int c2 = __float_as_int(m23.x), c3 = __float_as_int(m23.z);
    int c4 = __float_as_int(m45.x), c5 = __float_as_int(m45.z);
    int c6 = __float_as_int(m67.x), c7 = __float_as_int(m67.z);
    float v0 = (deg > 0) ? m01.y : 0.0f;
    float v1 = (deg > 1) ? m01.w : 0.0f;
    float v2 = (deg > 2) ? m23.y : 0.0f;
    float v3 = (deg > 3) ? m23.w : 0.0f;
    float v4 = (deg > 4) ? m45.y : 0.0f;
    float v5 = (deg > 5) ? m45.w : 0.0f;
    float v6 = (deg > 6) ? m67.y : 0.0f;
    float v7 = (deg > 7) ? m67.w : 0.0f;

    // ---- wave 2: 8 independent 8B gathers from fp16 copy ----
    uint2 u0 = *(reinterpret_cast<const uint2*>(g_xh + (size_t)c0 * EMB) + lane);
    uint2 u1 = *(reinterpret_cast<const uint2*>(g_xh + (size_t)c1 * EMB) + lane);
    uint2 u2 = *(reinterpret_cast<const uint2*>(g_xh + (size_t)c2 * EMB) + lane);
    uint2 u3 = *(reinterpret_cast<const uint2*>(g_xh + (size_t)c3 * EMB) + lane);
    uint2 u4 = *(reinterpret_cast<const uint2*>(g_xh + (size_t)c4 * EMB) + lane);
    uint2 u5 = *(reinterpret_cast<const uint2*>(g_xh + (size_t)c5 * EMB) + lane);
    uint2 u6 = *(reinterpret_cast<const uint2*>(g_xh + (size_t)c6 * EMB) + lane);
    uint2 u7 = *(reinterpret_cast<const uint2*>(g_xh + (size_t)c7 * EMB) + lane);

    float4 acc;
    acc.x = ev.x - xv.x;
    acc.y = ev.y - xv.y;
    acc.z = ev.z - xv.z;
    acc.w = ev.w - xv.w;

    {
        float2 fa, fb;
        fa = __half22float2(*reinterpret_cast<__half2*>(&u0.x));
        fb = __half22float2(*reinterpret_cast<__half2*>(&u0.y));
        acc.x += v0 * fa.x; acc.y += v0 * fa.y; acc.z += v0 * fb.x; acc.w += v0 * fb.y;
        fa = __half22float2(*reinterpret_cast<__half2*>(&u1.x));
        fb = __half22float2(*reinterpret_cast<__half2*>(&u1.y));
        acc.x += v1 * fa.x; acc.y += v1 * fa.y; acc.z += v1 * fb.x; acc.w += v1 * fb.y;
        fa = __half22float2(*reinterpret_cast<__half2*>(&u2.x));
        fb = __half22float2(*reinterpret_cast<__half2*>(&u2.y));
        acc.x += v2 * fa.x; acc.y += v2 * fa.y; acc.z += v2 * fb.x; acc.w += v2 * fb.y;
        fa = __half22float2(*reinterpret_cast<__half2*>(&u3.x));
        fb = __half22float2(*reinterpret_cast<__half2*>(&u3.y));
        acc.x += v3 * fa.x; acc.y += v3 * fa.y; acc.z += v3 * fb.x; acc.w += v3 * fb.y;
        fa = __half22float2(*reinterpret_cast<__half2*>(&u4.x));
        fb = __half22float2(*reinterpret_cast<__half2*>(&u4.y));
        acc.x += v4 * fa.x; acc.y += v4 * fa.y; acc.z += v4 * fb.x; acc.w += v4 * fb.y;
        fa = __half22float2(*reinterpret_cast<__half2*>(&u5.x));
        fb = __half22float2(*reinterpret_cast<__half2*>(&u5.y));
        acc.x += v5 * fa.x; acc.y += v5 * fa.y; acc.z += v5 * fb.x; acc.w += v5 * fb.y;
        fa = __half22float2(*reinterpret_cast<__half2*>(&u6.x));
        fb = __half22float2(*reinterpret_cast<__half2*>(&u6.y));
        acc.x += v6 * fa.x; acc.y += v6 * fa.y; acc.z += v6 * fb.x; acc.w += v6 * fb.y;
        fa = __half22float2(*reinterpret_cast<__half2*>(&u7.x));
        fb = __half22float2(*reinterpret_cast<__half2*>(&u7.y));
        acc.x += v7 * fa.x; acc.y += v7 * fa.y; acc.z += v7 * fb.x; acc.w += v7 * fb.y;
    }

    // ---- rare tail: deg > 8 (~18% of nodes), 2-wide fp16 loop ----
    for (int j = 8; j < deg; j += 2) {
        float4 m = *reinterpret_cast<const float4*>(ebase + j);
        int   ca = __float_as_int(m.x), cb = __float_as_int(m.z);
        float va = m.y;
        float vb = (j + 1 < deg) ? m.w : 0.0f;
        uint2 ua = *(reinterpret_cast<const uint2*>(g_xh + (size_t)ca * EMB) + lane);
        uint2 ub = *(reinterpret_cast<const uint2*>(g_xh + (size_t)cb * EMB) + lane);
        float2 fa = __half22float2(*reinterpret_cast<__half2*>(&ua.x));
        float2 fb = __half22float2(*reinterpret_cast<__half2*>(&ua.y));
        acc.x += va * fa.x; acc.y += va * fa.y; acc.z += va * fb.x; acc.w += va * fb.y;
        fa = __half22float2(*reinterpret_cast<__half2*>(&ub.x));
        fb = __half22float2(*reinterpret_cast<__half2*>(&ub.y));
        acc.x += vb * fa.x; acc.y += vb * fa.y; acc.z += vb * fb.x; acc.w += vb * fb.y;
    }

    reinterpret_cast<float4*>(out + (size_t)n * EMB)[lane] = acc;
}

extern "C" void kernel_launch(void* const* d_in, const int* in_sizes, int n_in,
                              void* d_out, int out_size) {
    // metadata order: t, x, e, hg_vals, hg_rows, hg_cols
    const float* x    = (const float*)d_in[1];
    const float* emb  = (const float*)d_in[2];
    const float* vals = (const float*)d_in[3];
    const int*   rows = (const int*)d_in[4];
    const int*   cols = (const int*)d_in[5];
    float* out = (float*)d_out;

    void* count_ptr = nullptr;
    cudaGetSymbolAddress(&count_ptr, g_count);
    cudaMemsetAsync(count_ptr, 0, N_NODES * sizeof(int));

    build_kernel<<<SCAT_BLOCKS + CONV_BLOCKS, 256>>>(vals, rows, cols, x);
    gather_kernel<<<(N_NODES * 32 + 255) / 256, 256>>>(x, emb, out);
}

// round 17
// speedup vs baseline: 1.1523x; 1.1523x over previous
#include <cuda_runtime.h>
#include <cuda_fp16.h>
#include <cstdint>

#define N_NODES 100000
#define N_EDGES 625000
#define EMB     128
#define SCALE   0.4f   // alpha/2
#define CAP     24     // Poisson(6.25): P(deg>=24) ~ 4e-9 per node; guarded anyway

#define SCAT_BLOCKS  ((N_EDGES + 255) / 256)             // 2442
#define CONV_THREADS (N_NODES * EMB / 8)                  // 1,600,000 (8 elems/thread)
#define CONV_BLOCKS  ((CONV_THREADS + 255) / 256)         // 6250

// Device scratch (allocation-free rule: __device__ globals)
__device__ int    g_count[N_NODES];               // degree histogram == alloc cursor
__device__ float2 g_edge[(size_t)N_NODES * CAP];  // (col bits, pre-scaled val)
__device__ __half g_xh[(size_t)N_NODES * EMB];    // fp16 copy of x, 25.6 MB

// ---- 1. fused build: scatter blocks + x->fp16 convert blocks in ONE launch ----
__global__ void build_kernel(const float* __restrict__ vals,
                             const int*  __restrict__ rows,
                             const int*  __restrict__ cols,
                             const float* __restrict__ x) {
    int b = blockIdx.x;
    if (b < SCAT_BLOCKS) {
        int i = b * 256 + threadIdx.x;
        if (i < N_EDGES) {
            int   r = rows[i];
            int   c = cols[i];
            float v = vals[i] * SCALE;
            int p = atomicAdd(&g_count[r], 1);
            if (p < CAP) g_edge[(size_t)r * CAP + p] = make_float2(__int_as_float(c), v);
        }
    } else {
        int i = (b - SCAT_BLOCKS) * 256 + threadIdx.x;   // 8 floats per thread
        if (i < CONV_THREADS) {
            float4 a0 = reinterpret_cast<const float4*>(x)[i * 2];
            float4 a1 = reinterpret_cast<const float4*>(x)[i * 2 + 1];
            __half2 h0 = __floats2half2_rn(a0.x, a0.y);
            __half2 h1 = __floats2half2_rn(a0.z, a0.w);
            __half2 h2 = __floats2half2_rn(a1.x, a1.y);
            __half2 h3 = __floats2half2_rn(a1.z, a1.w);
            uint4 o;
            o.x = *reinterpret_cast<uint32_t*>(&h0);
            o.y = *reinterpret_cast<uint32_t*>(&h1);
            o.z = *reinterpret_cast<uint32_t*>(&h2);
            o.w = *reinterpret_cast<uint32_t*>(&h3);
            reinterpret_cast<uint4*>(g_xh)[i] = o;
        }
    }
}

// ---- 2. gather: one warp/node, two stall waves, 8 fp16 gathers in flight ----
// Own row also read from the fp16 copy (saves the 51MB fp32 own-x stream).
// Slots >= deg are zero-init (col=0, safe) and masked by v=0.
__global__ void __launch_bounds__(256, 7) gather_kernel(
        const float* __restrict__ emb,
        float* __restrict__ out) {
    int lane = threadIdx.x & 31;
    int n = (blockIdx.x * blockDim.x + threadIdx.x) >> 5;
    if (n >= N_NODES) return;

    const float2* ebase = g_edge + (size_t)n * CAP;

    // ---- wave 1: issue everything independent ----
    int    deg = g_count[n];
    float4 m01 = *reinterpret_cast<const float4*>(ebase);       // slots 0,1
    float4 m23 = *reinterpret_cast<const float4*>(ebase + 2);   // slots 2,3
    float4 m45 = *reinterpret_cast<const float4*>(ebase + 4);   // slots 4,5
    float4 m67 = *reinterpret_cast<const float4*>(ebase + 6);   // slots 6,7
    uint2  xo  = *(reinterpret_cast<const uint2*>(g_xh + (size_t)n * EMB) + lane);
    float4 ev  = reinterpret_cast<const float4*>(emb + (size_t)n * EMB)[lane];

    if (deg > CAP) deg = CAP;

    int c0 = __float_as_int(m01.x), c1 = __float_as_int(m01.z);
    int c2 = __float_as_int(m23.x), c3 = __float_as_int(m23.z);
    int c4 = __float_as_int(m45.x), c5 = __float_as_int(m45.z);
    int c6 = __float_as_int(m67.x), c7 = __float_as_int(m67.z);
    float v0 = (deg > 0) ? m01.y : 0.0f;
    float v1 = (deg > 1) ? m01.w : 0.0f;
    float v2 = (deg > 2) ? m23.y : 0.0f;
    float v3 = (deg > 3) ? m23.w : 0.0f;
    float v4 = (deg > 4) ? m45.y : 0.0f;
    float v5 = (deg > 5) ? m45.w : 0.0f;
    float v6 = (deg > 6) ? m67.y : 0.0f;
    float v7 = (deg > 7) ? m67.w : 0.0f;

    // ---- wave 2: 8 independent 8B gathers from fp16 copy ----
    uint2 u0 = *(reinterpret_cast<const uint2*>(g_xh + (size_t)c0 * EMB) + lane);
    uint2 u1 = *(reinterpret_cast<const uint2*>(g_xh + (size_t)c1 * EMB) + lane);
    uint2 u2 = *(reinterpret_cast<const uint2*>(g_xh + (size_t)c2 * EMB) + lane);
    uint2 u3 = *(reinterpret_cast<const uint2*>(g_xh + (size_t)c3 * EMB) + lane);
    uint2 u4 = *(reinterpret_cast<const uint2*>(g_xh + (size_t)c4 * EMB) + lane);
    uint2 u5 = *(reinterpret_cast<const uint2*>(g_xh + (size_t)c5 * EMB) + lane);
    uint2 u6 = *(reinterpret_cast<const uint2*>(g_xh + (size_t)c6 * EMB) + lane);
    uint2 u7 = *(reinterpret_cast<const uint2*>(g_xh + (size_t)c7 * EMB) + lane);

    float2 oa = __half22float2(*reinterpret_cast<__half2*>(&xo.x));
    float2 ob = __half22float2(*reinterpret_cast<__half2*>(&xo.y));
    float4 acc;
    acc.x = ev.x - oa.x;
    acc.y = ev.y - oa.y;
    acc.z = ev.z - ob.x;
    acc.w = ev.w - ob.y;

    {
        float2 fa, fb;
        fa = __half22float2(*reinterpret_cast<__half2*>(&u0.x));
        fb = __half22float2(*reinterpret_cast<__half2*>(&u0.y));
        acc.x += v0 * fa.x; acc.y += v0 * fa.y; acc.z += v0 * fb.x; acc.w += v0 * fb.y;
        fa = __half22float2(*reinterpret_cast<__half2*>(&u1.x));
        fb = __half22float2(*reinterpret_cast<__half2*>(&u1.y));
        acc.x += v1 * fa.x; acc.y += v1 * fa.y; acc.z += v1 * fb.x; acc.w += v1 * fb.y;
        fa = __half22float2(*reinterpret_cast<__half2*>(&u2.x));
        fb = __half22float2(*reinterpret_cast<__half2*>(&u2.y));
        acc.x += v2 * fa.x; acc.y += v2 * fa.y; acc.z += v2 * fb.x; acc.w += v2 * fb.y;
        fa = __half22float2(*reinterpret_cast<__half2*>(&u3.x));
        fb = __half22float2(*reinterpret_cast<__half2*>(&u3.y));
        acc.x += v3 * fa.x; acc.y += v3 * fa.y; acc.z += v3 * fb.x; acc.w += v3 * fb.y;
        fa = __half22float2(*reinterpret_cast<__half2*>(&u4.x));
        fb = __half22float2(*reinterpret_cast<__half2*>(&u4.y));
        acc.x += v4 * fa.x; acc.y += v4 * fa.y; acc.z += v4 * fb.x; acc.w += v4 * fb.y;
        fa = __half22float2(*reinterpret_cast<__half2*>(&u5.x));
        fb = __half22float2(*reinterpret_cast<__half2*>(&u5.y));
        acc.x += v5 * fa.x; acc.y += v5 * fa.y; acc.z += v5 * fb.x; acc.w += v5 * fb.y;
        fa = __half22float2(*reinterpret_cast<__half2*>(&u6.x));
        fb = __half22float2(*reinterpret_cast<__half2*>(&u6.y));
        acc.x += v6 * fa.x; acc.y += v6 * fa.y; acc.z += v6 * fb.x; acc.w += v6 * fb.y;
        fa = __half22float2(*reinterpret_cast<__half2*>(&u7.x));
        fb = __half22float2(*reinterpret_cast<__half2*>(&u7.y));
        acc.x += v7 * fa.x; acc.y += v7 * fa.y; acc.z += v7 * fb.x; acc.w += v7 * fb.y;
    }

    // ---- rare tail: deg > 8 (~18% of nodes), 2-wide fp16 loop ----
    for (int j = 8; j < deg; j += 2) {
        float4 m = *reinterpret_cast<const float4*>(ebase + j);
        int   ca = __float_as_int(m.x), cb = __float_as_int(m.z);
        float va = m.y;
        float vb = (j + 1 < deg) ? m.w : 0.0f;
        uint2 ua = *(reinterpret_cast<const uint2*>(g_xh + (size_t)ca * EMB) + lane);
        uint2 ub = *(reinterpret_cast<const uint2*>(g_xh + (size_t)cb * EMB) + lane);
        float2 fa = __half22float2(*reinterpret_cast<__half2*>(&ua.x));
        float2 fb = __half22float2(*reinterpret_cast<__half2*>(&ua.y));
        acc.x += va * fa.x; acc.y += va * fa.y; acc.z += va * fb.x; acc.w += va * fb.y;
        fa = __half22float2(*reinterpret_cast<__half2*>(&ub.x));
        fb = __half22float2(*reinterpret_cast<__half2*>(&ub.y));
        acc.x += vb * fa.x; acc.y += vb * fa.y; acc.z += vb * fb.x; acc.w += vb * fb.y;
    }

    reinterpret_cast<float4*>(out + (size_t)n * EMB)[lane] = acc;
}

extern "C" void kernel_launch(void* const* d_in, const int* in_sizes, int n_in,
                              void* d_out, int out_size) {
    // metadata order: t, x, e, hg_vals, hg_rows, hg_cols
    const float* x    = (const float*)d_in[1];
    const float* emb  = (const float*)d_in[2];
    const float* vals = (const float*)d_in[3];
    const int*   rows = (const int*)d_in[4];
    const int*   cols = (const int*)d_in[5];
    float* out = (float*)d_out;

    void* count_ptr = nullptr;
    cudaGetSymbolAddress(&count_ptr, g_count);
    cudaMemsetAsync(count_ptr, 0, N_NODES * sizeof(int));

    build_kernel<<<SCAT_BLOCKS + CONV_BLOCKS, 256>>>(vals, rows, cols, x);
    gather_kernel<<<(N_NODES * 32 + 255) / 256, 256>>>(emb, out);
}